// round 14
// baseline (speedup 1.0000x reference)
#include <cuda_runtime.h>
#include <cstdint>

#define BATCH 16
#define CH    256
#define HW    64
#define NPIX  (HW * HW)
#define STAGES 8          // ring: 4 groups x 2 channels

typedef unsigned long long u64;

union F4U { float4 f; ulonglong2 u; };

__device__ __forceinline__ u64 pk2(float lo, float hi) {
    u64 r;
    asm("mov.b64 %0, {%1, %2};" : "=l"(r) : "f"(lo), "f"(hi));
    return r;
}
__device__ __forceinline__ void upk2(u64 v, float &lo, float &hi) {
    asm("mov.b64 {%0, %1}, %2;" : "=f"(lo), "=f"(hi) : "l"(v));
}
__device__ __forceinline__ void ffma2(u64 &d, u64 a, u64 b) {
    asm("fma.rn.f32x2 %0, %1, %2, %0;" : "+l"(d) : "l"(a), "l"(b));
}
__device__ __forceinline__ void cp16z(uint32_t dst, const float* src, int srcsz) {
    asm volatile("cp.async.cg.shared.global [%0], [%1], 16, %2;"
                 :: "r"(dst), "l"(src), "r"(srcsz));
}
__device__ __forceinline__ void cp_commit() {
    asm volatile("cp.async.commit_group;");
}
__device__ __forceinline__ void cp_wait2() {
    asm volatile("cp.async.wait_group 2;" ::: "memory");
}

// slot permutation: data chunk c (0..15) -> slot 1+c+(c>>3); slot 9 = zero guard.
// Conflict-free per quarter-warp for every access class (enumerated mod 8).
#define SLOT(c) (1 + (c) + ((c) >> 3))
#define STAGE_F4 (16 * 18)            // float4 per stage

// out[b, oi*9+oj, i, j] = (1/C) * sum_c x[b,c,i,j] * y[b,c,i+oi-4, j+oj-4]
// Block: 288 thr = 9 warps (warp = oi), covers b, output rows i0..i0+3.
// Pipeline shape of round 8/12 (2 ch per wait_group-2 + barrier), unrolled x4
// so all stage indices are compile-time immediates (no ring IMADs).
__global__ __launch_bounds__(288, 2)
void corr_kernel(const float* __restrict__ x, const float* __restrict__ y,
                 float* __restrict__ out) {
    __shared__ float4 sm[STAGES][16][18];

    const int tid = threadIdx.x;
    const int b   = blockIdx.y;
    const int i0  = blockIdx.x * 4;

    // zero the shared guard slot (slot 9) in all stages/rows
    if (tid < 128) sm[tid >> 4][tid & 15][9] = make_float4(0.f, 0.f, 0.f, 0.f);

    // ---- cooperative loader setup (one 16B chunk per thread, tid < 256) ----
    const bool isload = tid < 256;
    const int  lrow = (tid >> 4) & 15;    // local row 0..15
    const int  lck  = tid & 15;           // data chunk 0..15
    const bool isx  = lrow >= 12;
    int grow = isx ? (i0 + lrow - 12) : (i0 - 4 + lrow);
    const bool valid = isx || ((unsigned)grow < (unsigned)HW);
    if (!valid) grow = 0;
    const float* gsrc = (isx ? x : y) + (size_t)b * CH * NPIX + grow * HW + lck * 4;
    const int srcsz = valid ? 16 : 0;
    const uint32_t stage_b = STAGE_F4 * 16;    // bytes per stage
    const uint32_t sdst =
        (uint32_t)__cvta_generic_to_shared(&sm[0][lrow][SLOT(lck)]);

    // ---- prologue: 3 groups x 2 channels (ch 0..5 -> stages 0..5) ----
    #pragma unroll
    for (int g = 0; g < 3; ++g) {
        if (isload) {
            cp16z(sdst + (uint32_t)(2 * g)     * stage_b, gsrc + (size_t)(2 * g)     * NPIX, srcsz);
            cp16z(sdst + (uint32_t)(2 * g + 1) * stage_b, gsrc + (size_t)(2 * g + 1) * NPIX, srcsz);
        }
        cp_commit();
    }

    // ---- compute-lane constants ----
    const int lane = tid & 31;
    const int jg   = lane & 7;        // j0 = 8*jg
    const int ro   = lane >> 3;       // output row i0+ro
    const int oi   = tid >> 5;        // 0..8
    const int srow = ro + oi;         // y row in smem (0..11)
    const int yc0  = (jg == 0) ? 9 : SLOT(2 * jg - 1);
    const int yc1  = SLOT(2 * jg);
    const int yc2  = SLOT(2 * jg + 1);
    const int yc3  = (jg == 7) ? 9 : SLOT(2 * jg + 2);
    const int xrow = 12 + ro;

    // stage-0 base pointers; other stages via compile-time offsets
    const float4* pW0 = &sm[0][srow][yc0];
    const float4* pW1 = &sm[0][srow][yc1];
    const float4* pW2 = &sm[0][srow][yc2];
    const float4* pW3 = &sm[0][srow][yc3];
    const float4* pXA = &sm[0][xrow][yc1];
    const float4* pXB = &sm[0][xrow][yc2];

    // Accumulators: even oj=2e pairs (2t,2t+1); odd oj=2o+1 pairs (2p+1,2p+2)
    // + scalar pixels 0 and 7.
    u64   aE[5][4], aO[4][3];
    float s0[4], s7[4];
    #pragma unroll
    for (int e = 0; e < 5; ++e)
        #pragma unroll
        for (int t = 0; t < 4; ++t) aE[e][t] = 0ull;
    #pragma unroll
    for (int o = 0; o < 4; ++o) {
        s0[o] = 0.f; s7[o] = 0.f;
        #pragma unroll
        for (int p = 0; p < 3; ++p) aO[o][p] = 0ull;
    }

#define COMPUTE_CH(ST)                                                         \
    {                                                                          \
        F4U w0, w1, w2, w3, xa, xb;                                            \
        w0.f = pW0[(ST) * STAGE_F4];                                           \
        w1.f = pW1[(ST) * STAGE_F4];                                           \
        w2.f = pW2[(ST) * STAGE_F4];                                           \
        w3.f = pW3[(ST) * STAGE_F4];                                           \
        xa.f = pXA[(ST) * STAGE_F4];                                           \
        xb.f = pXB[(ST) * STAGE_F4];                                           \
        u64 X[4];   /* register-pair aliases: no MOVs */                       \
        X[0] = xa.u.x; X[1] = xa.u.y; X[2] = xb.u.x; X[3] = xb.u.y;            \
        u64 E[8];                                                              \
        E[0] = w0.u.x; E[1] = w0.u.y; E[2] = w1.u.x; E[3] = w1.u.y;            \
        E[4] = w2.u.x; E[5] = w2.u.y; E[6] = w3.u.x; E[7] = w3.u.y;            \
        u64 XO[3];  /* odd pixel pairs (1,2)(3,4)(5,6) */                      \
        XO[0] = pk2(xa.f.y, xa.f.z);                                           \
        XO[1] = pk2(xa.f.w, xb.f.x);                                           \
        XO[2] = pk2(xb.f.y, xb.f.z);                                           \
        _Pragma("unroll")                                                      \
        for (int e = 0; e < 5; ++e)                                            \
            _Pragma("unroll")                                                  \
            for (int t = 0; t < 4; ++t) ffma2(aE[e][t], X[t], E[e + t]);       \
        _Pragma("unroll")                                                      \
        for (int o = 0; o < 4; ++o)                                            \
            _Pragma("unroll")                                                  \
            for (int p = 0; p < 3; ++p) ffma2(aO[o][p], XO[p], E[p + o + 1]);  \
        s0[0] = fmaf(xa.f.x, w0.f.y, s0[0]);                                   \
        s0[1] = fmaf(xa.f.x, w0.f.w, s0[1]);                                   \
        s0[2] = fmaf(xa.f.x, w1.f.y, s0[2]);                                   \
        s0[3] = fmaf(xa.f.x, w1.f.w, s0[3]);                                   \
        s7[0] = fmaf(xb.f.w, w2.f.x, s7[0]);                                   \
        s7[1] = fmaf(xb.f.w, w2.f.z, s7[1]);                                   \
        s7[2] = fmaf(xb.f.w, w3.f.x, s7[2]);                                   \
        s7[3] = fmaf(xb.f.w, w3.f.z, s7[3]);                                   \
    }

// one pipeline step: wait, barrier, compute 2 channels, refill 2 stages, commit
#define STEP(SA, SB, RA, RB, CHA, DO_REFILL)                                   \
    {                                                                          \
        cp_wait2();                                                            \
        __syncthreads();                                                       \
        COMPUTE_CH(SA);                                                        \
        COMPUTE_CH(SB);                                                        \
        if (isload && (DO_REFILL)) {                                           \
            cp16z(sdst + (uint32_t)(RA) * stage_b, gnext,        srcsz);       \
            cp16z(sdst + (uint32_t)(RB) * stage_b, gnext + NPIX, srcsz);       \
        }                                                                      \
        cp_commit();                                                           \
        gnext += 2 * NPIX;                                                     \
    }

    const float* gnext = gsrc + (size_t)6 * NPIX;   // next channel to fetch

    #pragma unroll 1
    for (int k = 0; k < CH / 8; ++k) {
        const bool more = (k < CH / 8 - 1);
        STEP(0, 1, 6, 7, 8 * k + 6, true);    // ch 8k+6,8k+7 (always valid)
        STEP(2, 3, 0, 1, 8 * k + 8, more);
        STEP(4, 5, 2, 3, 8 * k + 10, more);
        STEP(6, 7, 4, 5, 8 * k + 12, more);
    }
#undef STEP
#undef COMPUTE_CH

    // ---- epilogue ----
    const float sc = 1.0f / (float)CH;
    float* ob = out + (((size_t)b * 81 + (size_t)oi * 9) * HW + (i0 + ro)) * HW
                    + 8 * jg;
    #pragma unroll
    for (int e = 0; e < 5; ++e) {            // oj = 2e
        float v[8];
        #pragma unroll
        for (int t = 0; t < 4; ++t) upk2(aE[e][t], v[2 * t], v[2 * t + 1]);
        float* op = ob + (size_t)(2 * e) * NPIX;
        *(float4*)op       = make_float4(v[0] * sc, v[1] * sc, v[2] * sc, v[3] * sc);
        *(float4*)(op + 4) = make_float4(v[4] * sc, v[5] * sc, v[6] * sc, v[7] * sc);
    }
    #pragma unroll
    for (int o = 0; o < 4; ++o) {            // oj = 2o+1
        float v[8];
        v[0] = s0[o];
        #pragma unroll
        for (int p = 0; p < 3; ++p) upk2(aO[o][p], v[2 * p + 1], v[2 * p + 2]);
        v[7] = s7[o];
        float* op = ob + (size_t)(2 * o + 1) * NPIX;
        *(float4*)op       = make_float4(v[0] * sc, v[1] * sc, v[2] * sc, v[3] * sc);
        *(float4*)(op + 4) = make_float4(v[4] * sc, v[5] * sc, v[6] * sc, v[7] * sc);
    }
}

extern "C" void kernel_launch(void* const* d_in, const int* in_sizes, int n_in,
                              void* d_out, int out_size) {
    const float* x = (const float*)d_in[0];
    const float* y = (const float*)d_in[1];
    float* out = (float*)d_out;
    dim3 grid(HW / 4, BATCH);   // 16 row-groups x 16 batches = 256 blocks
    corr_kernel<<<grid, 288>>>(x, y, out);
}

// round 16
// speedup vs baseline: 1.0709x; 1.0709x over previous
#include <cuda_runtime.h>
#include <cstdint>

#define BATCH 16
#define CH    256
#define HW    64
#define NPIX  (HW * HW)
#define STAGES 8          // ring depth (4 groups x 2 channels)

typedef unsigned long long u64;

union F4U { float4 f; ulonglong2 u; };

__device__ __forceinline__ u64 pk2(float lo, float hi) {
    u64 r;
    asm("mov.b64 %0, {%1, %2};" : "=l"(r) : "f"(lo), "f"(hi));
    return r;
}
__device__ __forceinline__ void upk2(u64 v, float &lo, float &hi) {
    asm("mov.b64 {%0, %1}, %2;" : "=f"(lo), "=f"(hi) : "l"(v));
}
__device__ __forceinline__ void ffma2(u64 &d, u64 a, u64 b) {
    asm("fma.rn.f32x2 %0, %1, %2, %0;" : "+l"(d) : "l"(a), "l"(b));
}
__device__ __forceinline__ void cp16z(uint32_t dst, const float* src, int srcsz) {
    asm volatile("cp.async.cg.shared.global [%0], [%1], 16, %2;"
                 :: "r"(dst), "l"(src), "r"(srcsz));
}
__device__ __forceinline__ void cp_commit() {
    asm volatile("cp.async.commit_group;");
}

// slot permutation: data chunk c (0..15) -> slot 1+c+(c>>3) in {1..8,10..17};
// slot 9 = shared zero guard (window chunk -1 and 16). Conflict-free per
// quarter-warp for every access class (verified by enumeration mod 8).
#define SLOT(c) (1 + (c) + ((c) >> 3))

// out[b, oi*9+oj, i, j] = (1/C) * sum_c x[b,c,i,j] * y[b,c,i+oi-4, j+oj-4]
// Block: 288 thr = 9 warps (warp = oi), covers b, output rows i0..i0+3.
// smem ring: STAGES x 16 rows (12 y rows i0-4..i0+7, 4 x rows i0..i0+3) x 18 slots.
// Round-8/12 pipeline shape (2 ch/group, wait_group 2, ~6 channels in flight).
// Change vs round 12: refill cp.async issued right after the barrier (before
// compute) to lengthen prefetch lead; safety unchanged (refilled stages were
// consumed in iteration k-1, all warps past barrier k).
__global__ __launch_bounds__(288, 2)
void corr_kernel(const float* __restrict__ x, const float* __restrict__ y,
                 float* __restrict__ out) {
    __shared__ float4 sm[STAGES][16][18];

    const int tid = threadIdx.x;
    const int b   = blockIdx.y;
    const int i0  = blockIdx.x * 4;

    // zero the shared guard slot (slot 9) in all stages/rows
    if (tid < 128) sm[tid >> 4][tid & 15][9] = make_float4(0.f, 0.f, 0.f, 0.f);

    // ---- cooperative loader setup (one 16B chunk per thread, tid < 256) ----
    const bool isload = tid < 256;
    const int  lrow = (tid >> 4) & 15;    // local row 0..15
    const int  lck  = tid & 15;           // data chunk 0..15
    const bool isx  = lrow >= 12;
    int grow = isx ? (i0 + lrow - 12) : (i0 - 4 + lrow);
    const bool valid = isx || ((unsigned)grow < (unsigned)HW);
    if (!valid) grow = 0;
    const float* gsrc = (isx ? x : y) + (size_t)b * CH * NPIX + grow * HW + lck * 4;
    const int srcsz = valid ? 16 : 0;
    const uint32_t stage_b = 16 * 18 * 16;     // bytes per stage
    const uint32_t sdst =
        (uint32_t)__cvta_generic_to_shared(&sm[0][lrow][SLOT(lck)]);

    // ---- prologue: 3 groups x 2 channels (ch 0..5 in flight) ----
    #pragma unroll
    for (int g = 0; g < 3; ++g) {
        if (isload) {
            cp16z(sdst + (uint32_t)(2 * g)     * stage_b, gsrc + (size_t)(2 * g)     * NPIX, srcsz);
            cp16z(sdst + (uint32_t)(2 * g + 1) * stage_b, gsrc + (size_t)(2 * g + 1) * NPIX, srcsz);
        }
        cp_commit();
    }

    // ---- compute-lane constants ----
    const int lane = tid & 31;
    const int jg   = lane & 7;        // j0 = 8*jg
    const int ro   = lane >> 3;       // output row i0+ro
    const int oi   = tid >> 5;        // 0..8
    const int srow = ro + oi;         // y row in smem (0..11)
    const int yc0  = (jg == 0) ? 9 : SLOT(2 * jg - 1);
    const int yc1  = SLOT(2 * jg);
    const int yc2  = SLOT(2 * jg + 1);
    const int yc3  = (jg == 7) ? 9 : SLOT(2 * jg + 2);
    const int xrow = 12 + ro;

    u64 aE[5][4], aO[4][4];
    #pragma unroll
    for (int e = 0; e < 5; ++e)
        #pragma unroll
        for (int t = 0; t < 4; ++t) aE[e][t] = 0ull;
    #pragma unroll
    for (int o = 0; o < 4; ++o)
        #pragma unroll
        for (int t = 0; t < 4; ++t) aO[o][t] = 0ull;

#define COMPUTE_CH(st)                                                         \
    {                                                                          \
        F4U w0, w1, w2, w3, xa, xb;                                            \
        w0.f = sm[st][srow][yc0];                                              \
        w1.f = sm[st][srow][yc1];                                              \
        w2.f = sm[st][srow][yc2];                                              \
        w3.f = sm[st][srow][yc3];                                              \
        xa.f = sm[st][xrow][yc1];                                              \
        xb.f = sm[st][xrow][yc2];                                              \
        u64 X[4];   /* register-pair aliases: no MOVs */                       \
        X[0] = xa.u.x; X[1] = xa.u.y; X[2] = xb.u.x; X[3] = xb.u.y;            \
        u64 E[8];                                                              \
        E[0] = w0.u.x; E[1] = w0.u.y; E[2] = w1.u.x; E[3] = w1.u.y;            \
        E[4] = w2.u.x; E[5] = w2.u.y; E[6] = w3.u.x; E[7] = w3.u.y;            \
        u64 O[7];   /* odd-aligned: genuine re-packs */                        \
        O[0] = pk2(w0.f.y, w0.f.z); O[1] = pk2(w0.f.w, w1.f.x);                \
        O[2] = pk2(w1.f.y, w1.f.z); O[3] = pk2(w1.f.w, w2.f.x);                \
        O[4] = pk2(w2.f.y, w2.f.z); O[5] = pk2(w2.f.w, w3.f.x);                \
        O[6] = pk2(w3.f.y, w3.f.z);                                            \
        _Pragma("unroll")                                                      \
        for (int e = 0; e < 5; ++e)                                            \
            _Pragma("unroll")                                                  \
            for (int t = 0; t < 4; ++t) ffma2(aE[e][t], X[t], E[e + t]);       \
        _Pragma("unroll")                                                      \
        for (int o = 0; o < 4; ++o)                                            \
            _Pragma("unroll")                                                  \
            for (int t = 0; t < 4; ++t) ffma2(aO[o][t], X[t], O[o + t]);       \
    }

    const float* gpre = gsrc + (size_t)6 * NPIX;

    #pragma unroll 1
    for (int k = 0; k < CH / 2; ++k) {
        // group k (channels 2k, 2k+1) complete; barrier publishes to all warps
        asm volatile("cp.async.wait_group 2;" ::: "memory");
        __syncthreads();

        // refill FIRST: stages (2k+6)&7, (2k+7)&7 were consumed in iteration
        // k-1 and every warp is past barrier k -> safe; issuing before compute
        // lengthens the prefetch lead by ~one compute phase.
        if (isload && (2 * k + 6 < CH)) {
            cp16z(sdst + (uint32_t)((2 * k + 6) & (STAGES - 1)) * stage_b, gpre, srcsz);
            cp16z(sdst + (uint32_t)((2 * k + 7) & (STAGES - 1)) * stage_b, gpre + NPIX, srcsz);
        }
        cp_commit();
        gpre += 2 * NPIX;

        const int st0 = (2 * k) & (STAGES - 1);
        COMPUTE_CH(st0);
        COMPUTE_CH(st0 + 1);          // (2k+1)&7 == st0+1 (st0 is even)
    }
#undef COMPUTE_CH

    // ---- epilogue ----
    const float sc = 1.0f / (float)CH;
    float* ob = out + (((size_t)b * 81 + (size_t)oi * 9) * HW + (i0 + ro)) * HW
                    + 8 * jg;
    #pragma unroll
    for (int e = 0; e < 5; ++e) {            // oj = 2e
        float v[8];
        #pragma unroll
        for (int t = 0; t < 4; ++t) upk2(aE[e][t], v[2 * t], v[2 * t + 1]);
        float* op = ob + (size_t)(2 * e) * NPIX;
        *(float4*)op       = make_float4(v[0] * sc, v[1] * sc, v[2] * sc, v[3] * sc);
        *(float4*)(op + 4) = make_float4(v[4] * sc, v[5] * sc, v[6] * sc, v[7] * sc);
    }
    #pragma unroll
    for (int o = 0; o < 4; ++o) {            // oj = 2o+1
        float v[8];
        #pragma unroll
        for (int t = 0; t < 4; ++t) upk2(aO[o][t], v[2 * t], v[2 * t + 1]);
        float* op = ob + (size_t)(2 * o + 1) * NPIX;
        *(float4*)op       = make_float4(v[0] * sc, v[1] * sc, v[2] * sc, v[3] * sc);
        *(float4*)(op + 4) = make_float4(v[4] * sc, v[5] * sc, v[6] * sc, v[7] * sc);
    }
}

extern "C" void kernel_launch(void* const* d_in, const int* in_sizes, int n_in,
                              void* d_out, int out_size) {
    const float* x = (const float*)d_in[0];
    const float* y = (const float*)d_in[1];
    float* out = (float*)d_out;
    dim3 grid(HW / 4, BATCH);   // 16 row-groups x 16 batches = 256 blocks
    corr_kernel<<<grid, 288>>>(x, y, out);
}